// round 5
// baseline (speedup 1.0000x reference)
#include <cuda_runtime.h>
#include <cuda_bf16.h>
#include <cstdint>

#define USER_NUM 100000
#define ITEM_NUM 50000
#define N_NODES  (USER_NUM + ITEM_NUM)   // 150000
#define EMB      64
#define TOT      (N_NODES * EMB)         // 9,600,000 floats
#define NNZ_MAX  4800000
#define SCAN_CHUNK 1024
#define NCHUNK   ((N_NODES + SCAN_CHUNK - 1) / SCAN_CHUNK)   // 147

// Static device scratch (no runtime allocation allowed)
__device__ float g_bufA[TOT];
__device__ float g_bufB[TOT];
__device__ int   g_rowptr[N_NODES + 1];
__device__ int   g_cursor[N_NODES];
__device__ int   g_counts[N_NODES];
__device__ int2  g_edges[NNZ_MAX];       // packed (col, val-bits), row-sorted
__device__ int   g_partial[256];
__device__ int   g_pex[256];

// ---------------------------------------------------------------------------
// zero the row histogram (tiny)
// ---------------------------------------------------------------------------
__global__ void zero_counts(int* __restrict__ counts) {
    int i = blockIdx.x * blockDim.x + threadIdx.x;
    if (i < N_NODES) counts[i] = 0;
}

// ---------------------------------------------------------------------------
// Counting-sort stage 1: per-row histogram
// ---------------------------------------------------------------------------
__global__ void hist_kernel(const int* __restrict__ row,
                            int* __restrict__ counts, int nnz) {
    int i = blockIdx.x * blockDim.x + threadIdx.x;
    if (i < nnz) atomicAdd(&counts[__ldcs(row + i)], 1);
}

// ---------------------------------------------------------------------------
// Counting-sort stage 2: 3-kernel exclusive scan of counts -> rowptr, cursor
// ---------------------------------------------------------------------------
__global__ void scan_reduce(const int* __restrict__ counts,
                            int* __restrict__ partial) {
    __shared__ int s[SCAN_CHUNK];
    int i = blockIdx.x * SCAN_CHUNK + threadIdx.x;
    s[threadIdx.x] = (i < N_NODES) ? counts[i] : 0;
    __syncthreads();
    for (int st = SCAN_CHUNK / 2; st > 0; st >>= 1) {
        if (threadIdx.x < st) s[threadIdx.x] += s[threadIdx.x + st];
        __syncthreads();
    }
    if (threadIdx.x == 0) partial[blockIdx.x] = s[0];
}

__global__ void scan_partials(const int* __restrict__ partial,
                              int* __restrict__ pex, int n) {
    __shared__ int s[256];
    int v = (threadIdx.x < n) ? partial[threadIdx.x] : 0;
    s[threadIdx.x] = v;
    __syncthreads();
    for (int st = 1; st < 256; st <<= 1) {
        int t = (threadIdx.x >= st) ? s[threadIdx.x - st] : 0;
        __syncthreads();
        s[threadIdx.x] += t;
        __syncthreads();
    }
    if (threadIdx.x < n) pex[threadIdx.x] = s[threadIdx.x] - v;   // exclusive
}

__global__ void scan_final(const int* __restrict__ counts,
                           const int* __restrict__ pex,
                           int* __restrict__ rowptr,
                           int* __restrict__ cursor, int nnz) {
    __shared__ int s[SCAN_CHUNK];
    int i = blockIdx.x * SCAN_CHUNK + threadIdx.x;
    int v = (i < N_NODES) ? counts[i] : 0;
    s[threadIdx.x] = v;
    __syncthreads();
    for (int st = 1; st < SCAN_CHUNK; st <<= 1) {
        int t = (threadIdx.x >= st) ? s[threadIdx.x - st] : 0;
        __syncthreads();
        s[threadIdx.x] += t;
        __syncthreads();
    }
    if (i < N_NODES) {
        int ex = pex[blockIdx.x] + s[threadIdx.x] - v;   // exclusive prefix
        rowptr[i] = ex;
        cursor[i] = ex;
    }
    if (i == 0) rowptr[N_NODES] = nnz;
}

// ---------------------------------------------------------------------------
// Counting-sort stage 3: scatter edges into row-sorted packed array
// ---------------------------------------------------------------------------
__global__ void scatter_kernel(const int* __restrict__ row,
                               const int* __restrict__ col,
                               const float* __restrict__ vals,
                               int* __restrict__ cursor,
                               int2* __restrict__ edges, int nnz) {
    int i = blockIdx.x * blockDim.x + threadIdx.x;
    if (i < nnz) {
        int r = __ldcs(row + i);
        int p = atomicAdd(&cursor[r], 1);
        edges[p] = make_int2(__ldcs(col + i), __float_as_int(__ldcs(vals + i)));
    }
}

// ---------------------------------------------------------------------------
// ego row address without materializing the concatenated buffer
// ---------------------------------------------------------------------------
__device__ __forceinline__ const float* ego_row(const float* __restrict__ user,
                                                const float* __restrict__ item,
                                                int node) {
    return (node < USER_NUM) ? user + (size_t)node * EMB
                             : item + (size_t)(node - USER_NUM) * EMB;
}

// ---------------------------------------------------------------------------
// CSR SpMM, warp per row, segmented register accumulation, NO atomics.
// Each lane owns a float2 of the 64-wide embedding. Edge metadata is a
// warp-uniform 8B load (16 edges/line -> mostly L1 hits).
// MODE 0: layer 1 — gather from user/item inputs directly; acc = ego + h1
// MODE 1: middle   — gather from buf; acc += h
// MODE 2: final    — gather from buf; acc = (acc + h) * 0.25, no y store
// ---------------------------------------------------------------------------
template<int MODE>
__global__ void spmm_csr(const int* __restrict__ rowptr,
                         const int2* __restrict__ edges,
                         const float* __restrict__ x,      // buf (MODE 1,2)
                         const float* __restrict__ user,   // MODE 0
                         const float* __restrict__ item,   // MODE 0
                         float* __restrict__ y,
                         float* __restrict__ acc) {
    int warp = (blockIdx.x * blockDim.x + threadIdx.x) >> 5;
    int lane = threadIdx.x & 31;
    if (warp >= N_NODES) return;

    int start = __ldg(rowptr + warp);
    int end   = __ldg(rowptr + warp + 1);

    float ax = 0.f, ay = 0.f;
    int e = start;

    #define XROW(c) (MODE == 0 ? ego_row(user, item, (c)) : x + (size_t)(c) * EMB)

    // 8-wide manual unroll for memory-level parallelism
    for (; e + 8 <= end; e += 8) {
        int2 ed[8];
        #pragma unroll
        for (int k = 0; k < 8; k++) ed[k] = __ldg(edges + e + k);
        float2 xv[8];
        #pragma unroll
        for (int k = 0; k < 8; k++)
            xv[k] = __ldg(reinterpret_cast<const float2*>(XROW(ed[k].x)) + lane);
        #pragma unroll
        for (int k = 0; k < 8; k++) {
            float v = __int_as_float(ed[k].y);
            ax = fmaf(v, xv[k].x, ax);
            ay = fmaf(v, xv[k].y, ay);
        }
    }
    for (; e < end; ++e) {
        int2 ed = __ldg(edges + e);
        float2 xv = __ldg(reinterpret_cast<const float2*>(XROW(ed.x)) + lane);
        float v = __int_as_float(ed.y);
        ax = fmaf(v, xv.x, ax);
        ay = fmaf(v, xv.y, ay);
    }
    #undef XROW

    float2* ap = reinterpret_cast<float2*>(acc + (size_t)warp * EMB) + lane;
    if (MODE == 0) {
        // acc = ego[row] + h1 ; y = h1
        float2 eg = __ldg(reinterpret_cast<const float2*>(ego_row(user, item, warp)) + lane);
        reinterpret_cast<float2*>(y + (size_t)warp * EMB)[lane] = make_float2(ax, ay);
        *ap = make_float2(eg.x + ax, eg.y + ay);
    } else if (MODE == 1) {
        float2 a = *ap;
        reinterpret_cast<float2*>(y + (size_t)warp * EMB)[lane] = make_float2(ax, ay);
        *ap = make_float2(a.x + ax, a.y + ay);
    } else {
        float2 a = *ap;
        *ap = make_float2((a.x + ax) * 0.25f, (a.y + ay) * 0.25f);
    }
}

extern "C" void kernel_launch(void* const* d_in, const int* in_sizes, int n_in,
                              void* d_out, int out_size) {
    const float* user_emb = (const float*)d_in[0];
    const float* item_emb = (const float*)d_in[1];
    const int*   adj_row  = (const int*)  d_in[2];
    const int*   adj_col  = (const int*)  d_in[3];
    const float* adj_vals = (const float*)d_in[4];
    float* out = (float*)d_out;
    int nnz = in_sizes[2];

    float* bufA;   cudaGetSymbolAddress((void**)&bufA,   g_bufA);
    float* bufB;   cudaGetSymbolAddress((void**)&bufB,   g_bufB);
    int*   rowptr; cudaGetSymbolAddress((void**)&rowptr, g_rowptr);
    int*   cursor; cudaGetSymbolAddress((void**)&cursor, g_cursor);
    int*   counts; cudaGetSymbolAddress((void**)&counts, g_counts);
    int2*  edges;  cudaGetSymbolAddress((void**)&edges,  g_edges);
    int*   partial;cudaGetSymbolAddress((void**)&partial,g_partial);
    int*   pex;    cudaGetSymbolAddress((void**)&pex,    g_pex);

    const int T = 256;
    const int ZC_BLOCKS = (N_NODES + T - 1) / T;
    const int EG_BLOCKS = (nnz + T - 1) / T;
    const int SP_BLOCKS = (N_NODES * 32 + T - 1) / T;    // warp per row

    // counting sort by row -> CSR (rowptr + packed (col,val) edges)
    zero_counts<<<ZC_BLOCKS, T>>>(counts);
    hist_kernel<<<EG_BLOCKS, T>>>(adj_row, counts, nnz);
    scan_reduce<<<NCHUNK, SCAN_CHUNK>>>(counts, partial);
    scan_partials<<<1, 256>>>(partial, pex, NCHUNK);
    scan_final<<<NCHUNK, SCAN_CHUNK>>>(counts, pex, rowptr, cursor, nnz);
    scatter_kernel<<<EG_BLOCKS, T>>>(adj_row, adj_col, adj_vals, cursor, edges, nnz);

    // layer 1: h1 = A*ego (reads inputs directly), acc = ego + h1, y=bufB
    spmm_csr<0><<<SP_BLOCKS, T>>>(rowptr, edges, nullptr, user_emb, item_emb, bufB, out);
    // layer 2: h2 = A*h1 (bufB->bufA), acc += h2
    spmm_csr<1><<<SP_BLOCKS, T>>>(rowptr, edges, bufB, nullptr, nullptr, bufA, out);
    // layer 3: h3 = A*h2 (bufA), acc = (acc + h3)/4
    spmm_csr<2><<<SP_BLOCKS, T>>>(rowptr, edges, bufA, nullptr, nullptr, nullptr, out);
}

// round 6
// speedup vs baseline: 1.3094x; 1.3094x over previous
#include <cuda_runtime.h>
#include <cuda_bf16.h>
#include <cstdint>

#define USER_NUM 100000
#define ITEM_NUM 50000
#define N_NODES  (USER_NUM + ITEM_NUM)   // 150000
#define EMB      64
#define TOT      (N_NODES * EMB)         // 9,600,000 floats
#define NNZ_MAX  4800000
#define SCAN_CHUNK 1024
#define NCHUNK   ((N_NODES + SCAN_CHUNK - 1) / SCAN_CHUNK)   // 147

// Static device scratch (no runtime allocation allowed)
__device__ float g_bufA[TOT];
__device__ float g_bufB[TOT];
__device__ int   g_rowptr[N_NODES + 1];
__device__ int   g_cursor[N_NODES];
__device__ int   g_counts[N_NODES];
__device__ int2  g_edges[NNZ_MAX];       // packed (col, val-bits), row-sorted
__device__ int   g_partial[256];
__device__ int   g_pex[256];

// ---------------------------------------------------------------------------
// zero the row histogram (tiny)
// ---------------------------------------------------------------------------
__global__ void zero_counts(int* __restrict__ counts) {
    int i = blockIdx.x * blockDim.x + threadIdx.x;
    if (i < N_NODES) counts[i] = 0;
}

// ---------------------------------------------------------------------------
// Counting-sort stage 1: per-row histogram
// ---------------------------------------------------------------------------
__global__ void hist_kernel(const int* __restrict__ row,
                            int* __restrict__ counts, int nnz) {
    int i = blockIdx.x * blockDim.x + threadIdx.x;
    if (i < nnz) atomicAdd(&counts[__ldcs(row + i)], 1);
}

// ---------------------------------------------------------------------------
// Counting-sort stage 2: 3-kernel exclusive scan of counts -> rowptr, cursor
// ---------------------------------------------------------------------------
__global__ void scan_reduce(const int* __restrict__ counts,
                            int* __restrict__ partial) {
    __shared__ int s[SCAN_CHUNK];
    int i = blockIdx.x * SCAN_CHUNK + threadIdx.x;
    s[threadIdx.x] = (i < N_NODES) ? counts[i] : 0;
    __syncthreads();
    for (int st = SCAN_CHUNK / 2; st > 0; st >>= 1) {
        if (threadIdx.x < st) s[threadIdx.x] += s[threadIdx.x + st];
        __syncthreads();
    }
    if (threadIdx.x == 0) partial[blockIdx.x] = s[0];
}

__global__ void scan_partials(const int* __restrict__ partial,
                              int* __restrict__ pex, int n) {
    __shared__ int s[256];
    int v = (threadIdx.x < n) ? partial[threadIdx.x] : 0;
    s[threadIdx.x] = v;
    __syncthreads();
    for (int st = 1; st < 256; st <<= 1) {
        int t = (threadIdx.x >= st) ? s[threadIdx.x - st] : 0;
        __syncthreads();
        s[threadIdx.x] += t;
        __syncthreads();
    }
    if (threadIdx.x < n) pex[threadIdx.x] = s[threadIdx.x] - v;   // exclusive
}

__global__ void scan_final(const int* __restrict__ counts,
                           const int* __restrict__ pex,
                           int* __restrict__ rowptr,
                           int* __restrict__ cursor, int nnz) {
    __shared__ int s[SCAN_CHUNK];
    int i = blockIdx.x * SCAN_CHUNK + threadIdx.x;
    int v = (i < N_NODES) ? counts[i] : 0;
    s[threadIdx.x] = v;
    __syncthreads();
    for (int st = 1; st < SCAN_CHUNK; st <<= 1) {
        int t = (threadIdx.x >= st) ? s[threadIdx.x - st] : 0;
        __syncthreads();
        s[threadIdx.x] += t;
        __syncthreads();
    }
    if (i < N_NODES) {
        int ex = pex[blockIdx.x] + s[threadIdx.x] - v;   // exclusive prefix
        rowptr[i] = ex;
        cursor[i] = ex;
    }
    if (i == 0) rowptr[N_NODES] = nnz;
}

// ---------------------------------------------------------------------------
// Counting-sort stage 3: scatter edges into row-sorted packed array
// ---------------------------------------------------------------------------
__global__ void scatter_kernel(const int* __restrict__ row,
                               const int* __restrict__ col,
                               const float* __restrict__ vals,
                               int* __restrict__ cursor,
                               int2* __restrict__ edges, int nnz) {
    int i = blockIdx.x * blockDim.x + threadIdx.x;
    if (i < nnz) {
        int r = __ldcs(row + i);
        int p = atomicAdd(&cursor[r], 1);
        edges[p] = make_int2(__ldcs(col + i), __float_as_int(__ldcs(vals + i)));
    }
}

// ---------------------------------------------------------------------------
// ego row address without materializing the concatenated buffer
// ---------------------------------------------------------------------------
__device__ __forceinline__ const float* ego_row(const float* __restrict__ user,
                                                const float* __restrict__ item,
                                                int node) {
    return (node < USER_NUM) ? user + (size_t)node * EMB
                             : item + (size_t)(node - USER_NUM) * EMB;
}

// ---------------------------------------------------------------------------
// CSR SpMM, warp per row, segmented register accumulation, NO atomics.
// Each lane owns a float2 of the 64-wide embedding. Edge metadata is a
// warp-uniform 8B load (16 edges/line -> mostly L1 hits).
// Unroll 4 (R4-proven; unroll 8 regressed via cross-CTA L1tex-queue spread).
// MODE 0: layer 1 — gather from user/item inputs directly; acc = ego + h1
// MODE 1: middle   — gather from buf; acc += h
// MODE 2: final    — gather from buf; acc = (acc + h) * 0.25, no y store
// ---------------------------------------------------------------------------
template<int MODE>
__global__ void spmm_csr(const int* __restrict__ rowptr,
                         const int2* __restrict__ edges,
                         const float* __restrict__ x,      // buf (MODE 1,2)
                         const float* __restrict__ user,   // MODE 0
                         const float* __restrict__ item,   // MODE 0
                         float* __restrict__ y,
                         float* __restrict__ acc) {
    int warp = (blockIdx.x * blockDim.x + threadIdx.x) >> 5;
    int lane = threadIdx.x & 31;
    if (warp >= N_NODES) return;

    int start = __ldg(rowptr + warp);
    int end   = __ldg(rowptr + warp + 1);

    float ax = 0.f, ay = 0.f;
    int e = start;

    #define XROW(c) (MODE == 0 ? ego_row(user, item, (c)) : x + (size_t)(c) * EMB)

    // 4-wide manual unroll for memory-level parallelism (R4 config)
    for (; e + 4 <= end; e += 4) {
        int2 e0 = __ldg(edges + e + 0);
        int2 e1 = __ldg(edges + e + 1);
        int2 e2 = __ldg(edges + e + 2);
        int2 e3 = __ldg(edges + e + 3);
        float2 x0 = __ldg(reinterpret_cast<const float2*>(XROW(e0.x)) + lane);
        float2 x1 = __ldg(reinterpret_cast<const float2*>(XROW(e1.x)) + lane);
        float2 x2 = __ldg(reinterpret_cast<const float2*>(XROW(e2.x)) + lane);
        float2 x3 = __ldg(reinterpret_cast<const float2*>(XROW(e3.x)) + lane);
        ax = fmaf(__int_as_float(e0.y), x0.x, ax);
        ay = fmaf(__int_as_float(e0.y), x0.y, ay);
        ax = fmaf(__int_as_float(e1.y), x1.x, ax);
        ay = fmaf(__int_as_float(e1.y), x1.y, ay);
        ax = fmaf(__int_as_float(e2.y), x2.x, ax);
        ay = fmaf(__int_as_float(e2.y), x2.y, ay);
        ax = fmaf(__int_as_float(e3.y), x3.x, ax);
        ay = fmaf(__int_as_float(e3.y), x3.y, ay);
    }
    for (; e < end; ++e) {
        int2 ed = __ldg(edges + e);
        float2 xv = __ldg(reinterpret_cast<const float2*>(XROW(ed.x)) + lane);
        float v = __int_as_float(ed.y);
        ax = fmaf(v, xv.x, ax);
        ay = fmaf(v, xv.y, ay);
    }
    #undef XROW

    float2* ap = reinterpret_cast<float2*>(acc + (size_t)warp * EMB) + lane;
    if (MODE == 0) {
        // acc = ego[row] + h1 ; y = h1
        float2 eg = __ldg(reinterpret_cast<const float2*>(ego_row(user, item, warp)) + lane);
        reinterpret_cast<float2*>(y + (size_t)warp * EMB)[lane] = make_float2(ax, ay);
        *ap = make_float2(eg.x + ax, eg.y + ay);
    } else if (MODE == 1) {
        float2 a = *ap;
        reinterpret_cast<float2*>(y + (size_t)warp * EMB)[lane] = make_float2(ax, ay);
        *ap = make_float2(a.x + ax, a.y + ay);
    } else {
        float2 a = *ap;
        *ap = make_float2((a.x + ax) * 0.25f, (a.y + ay) * 0.25f);
    }
}

extern "C" void kernel_launch(void* const* d_in, const int* in_sizes, int n_in,
                              void* d_out, int out_size) {
    const float* user_emb = (const float*)d_in[0];
    const float* item_emb = (const float*)d_in[1];
    const int*   adj_row  = (const int*)  d_in[2];
    const int*   adj_col  = (const int*)  d_in[3];
    const float* adj_vals = (const float*)d_in[4];
    float* out = (float*)d_out;
    int nnz = in_sizes[2];

    float* bufA;   cudaGetSymbolAddress((void**)&bufA,   g_bufA);
    float* bufB;   cudaGetSymbolAddress((void**)&bufB,   g_bufB);
    int*   rowptr; cudaGetSymbolAddress((void**)&rowptr, g_rowptr);
    int*   cursor; cudaGetSymbolAddress((void**)&cursor, g_cursor);
    int*   counts; cudaGetSymbolAddress((void**)&counts, g_counts);
    int2*  edges;  cudaGetSymbolAddress((void**)&edges,  g_edges);
    int*   partial;cudaGetSymbolAddress((void**)&partial,g_partial);
    int*   pex;    cudaGetSymbolAddress((void**)&pex,    g_pex);

    const int T = 256;
    const int ZC_BLOCKS = (N_NODES + T - 1) / T;
    const int EG_BLOCKS = (nnz + T - 1) / T;
    const int SP_BLOCKS = (N_NODES * 32 + T - 1) / T;    // warp per row

    // counting sort by row -> CSR (rowptr + packed (col,val) edges)
    zero_counts<<<ZC_BLOCKS, T>>>(counts);
    hist_kernel<<<EG_BLOCKS, T>>>(adj_row, counts, nnz);
    scan_reduce<<<NCHUNK, SCAN_CHUNK>>>(counts, partial);
    scan_partials<<<1, 256>>>(partial, pex, NCHUNK);
    scan_final<<<NCHUNK, SCAN_CHUNK>>>(counts, pex, rowptr, cursor, nnz);
    scatter_kernel<<<EG_BLOCKS, T>>>(adj_row, adj_col, adj_vals, cursor, edges, nnz);

    // layer 1: h1 = A*ego (reads inputs directly), acc = ego + h1, y=bufB
    spmm_csr<0><<<SP_BLOCKS, T>>>(rowptr, edges, nullptr, user_emb, item_emb, bufB, out);
    // layer 2: h2 = A*h1 (bufB->bufA), acc += h2
    spmm_csr<1><<<SP_BLOCKS, T>>>(rowptr, edges, bufB, nullptr, nullptr, bufA, out);
    // layer 3: h3 = A*h2 (bufA), acc = (acc + h3)/4
    spmm_csr<2><<<SP_BLOCKS, T>>>(rowptr, edges, bufA, nullptr, nullptr, nullptr, out);
}

// round 7
// speedup vs baseline: 1.5939x; 1.2173x over previous
#include <cuda_runtime.h>
#include <cuda_fp16.h>
#include <cuda_bf16.h>
#include <cstdint>

#define USER_NUM 100000
#define ITEM_NUM 50000
#define N_NODES  (USER_NUM + ITEM_NUM)   // 150000
#define EMB      64
#define TOT      (N_NODES * EMB)         // 9,600,000 elements
#define USER_ELEMS (USER_NUM * EMB)
#define NNZ_MAX  4800000
#define SCAN_CHUNK 1024
#define NCHUNK   ((N_NODES + SCAN_CHUNK - 1) / SCAN_CHUNK)   // 147

// Static device scratch (no runtime allocation allowed)
__device__ __half g_ego[TOT];            // fp16 copy of concat(user,item)
__device__ __half g_h1[TOT];             // layer-1 output (fp16)
__device__ __half g_h2[TOT];             // layer-2 output (fp16)
__device__ int   g_rowptr[N_NODES + 1];
__device__ int   g_cursor[N_NODES];
__device__ int   g_counts[N_NODES];
__device__ int2  g_edges[NNZ_MAX];       // packed (col, val-bits), row-sorted
__device__ int   g_partial[256];
__device__ int   g_pex[256];

// ---------------------------------------------------------------------------
// convert ego -> fp16 ; zero the row histogram (fused)
// ---------------------------------------------------------------------------
__global__ void convert_ego(const float2* __restrict__ user2,
                            const float2* __restrict__ item2,
                            __half2* __restrict__ ego2,
                            int* __restrict__ counts) {
    int i = blockIdx.x * blockDim.x + threadIdx.x;
    if (i < TOT / 2) {
        float2 v = (i < USER_ELEMS / 2) ? __ldg(user2 + i)
                                        : __ldg(item2 + (i - USER_ELEMS / 2));
        ego2[i] = __floats2half2_rn(v.x, v.y);
    }
    if (i < N_NODES) counts[i] = 0;
}

// ---------------------------------------------------------------------------
// Counting-sort stage 1: per-row histogram
// ---------------------------------------------------------------------------
__global__ void hist_kernel(const int* __restrict__ row,
                            int* __restrict__ counts, int nnz) {
    int i = blockIdx.x * blockDim.x + threadIdx.x;
    if (i < nnz) atomicAdd(&counts[__ldcs(row + i)], 1);
}

// ---------------------------------------------------------------------------
// Counting-sort stage 2: 3-kernel exclusive scan of counts -> rowptr, cursor
// ---------------------------------------------------------------------------
__global__ void scan_reduce(const int* __restrict__ counts,
                            int* __restrict__ partial) {
    __shared__ int s[SCAN_CHUNK];
    int i = blockIdx.x * SCAN_CHUNK + threadIdx.x;
    s[threadIdx.x] = (i < N_NODES) ? counts[i] : 0;
    __syncthreads();
    for (int st = SCAN_CHUNK / 2; st > 0; st >>= 1) {
        if (threadIdx.x < st) s[threadIdx.x] += s[threadIdx.x + st];
        __syncthreads();
    }
    if (threadIdx.x == 0) partial[blockIdx.x] = s[0];
}

__global__ void scan_partials(const int* __restrict__ partial,
                              int* __restrict__ pex, int n) {
    __shared__ int s[256];
    int v = (threadIdx.x < n) ? partial[threadIdx.x] : 0;
    s[threadIdx.x] = v;
    __syncthreads();
    for (int st = 1; st < 256; st <<= 1) {
        int t = (threadIdx.x >= st) ? s[threadIdx.x - st] : 0;
        __syncthreads();
        s[threadIdx.x] += t;
        __syncthreads();
    }
    if (threadIdx.x < n) pex[threadIdx.x] = s[threadIdx.x] - v;   // exclusive
}

__global__ void scan_final(const int* __restrict__ counts,
                           const int* __restrict__ pex,
                           int* __restrict__ rowptr,
                           int* __restrict__ cursor, int nnz) {
    __shared__ int s[SCAN_CHUNK];
    int i = blockIdx.x * SCAN_CHUNK + threadIdx.x;
    int v = (i < N_NODES) ? counts[i] : 0;
    s[threadIdx.x] = v;
    __syncthreads();
    for (int st = 1; st < SCAN_CHUNK; st <<= 1) {
        int t = (threadIdx.x >= st) ? s[threadIdx.x - st] : 0;
        __syncthreads();
        s[threadIdx.x] += t;
        __syncthreads();
    }
    if (i < N_NODES) {
        int ex = pex[blockIdx.x] + s[threadIdx.x] - v;   // exclusive prefix
        rowptr[i] = ex;
        cursor[i] = ex;
    }
    if (i == 0) rowptr[N_NODES] = nnz;
}

// ---------------------------------------------------------------------------
// Counting-sort stage 3: scatter edges into row-sorted packed array
// ---------------------------------------------------------------------------
__global__ void scatter_kernel(const int* __restrict__ row,
                               const int* __restrict__ col,
                               const float* __restrict__ vals,
                               int* __restrict__ cursor,
                               int2* __restrict__ edges, int nnz) {
    int i = blockIdx.x * blockDim.x + threadIdx.x;
    if (i < nnz) {
        int r = __ldcs(row + i);
        int p = atomicAdd(&cursor[r], 1);
        edges[p] = make_int2(__ldcs(col + i), __float_as_int(__ldcs(vals + i)));
    }
}

// ---------------------------------------------------------------------------
// CSR SpMM, warp per row, fp16 gather (128 B/edge), fp32 accumulation.
// Each lane owns a __half2 (2 consecutive dims). Unroll 4 (R4/R6-proven;
// unroll 8 regressed via cross-CTA L1tex-queue spread).
// FINAL=false: y[row] = h (fp16)
// FINAL=true : out[row] = (ego + h1 + h2 + h) * 0.25  (fp32), no y store
// ---------------------------------------------------------------------------
template<bool FINAL>
__global__ void spmm_csr(const int* __restrict__ rowptr,
                         const int2* __restrict__ edges,
                         const __half* __restrict__ x,     // gather source
                         __half* __restrict__ y,           // !FINAL
                         const __half* __restrict__ ego,   // FINAL
                         const __half* __restrict__ h1,    // FINAL
                         float* __restrict__ out) {        // FINAL
    int warp = (blockIdx.x * blockDim.x + threadIdx.x) >> 5;
    int lane = threadIdx.x & 31;
    if (warp >= N_NODES) return;

    int start = __ldg(rowptr + warp);
    int end   = __ldg(rowptr + warp + 1);

    float ax = 0.f, ay = 0.f;
    int e = start;

    #define XR(c) (reinterpret_cast<const __half2*>(x + (size_t)(c) * EMB) + lane)

    for (; e + 4 <= end; e += 4) {
        int2 e0 = __ldg(edges + e + 0);
        int2 e1 = __ldg(edges + e + 1);
        int2 e2 = __ldg(edges + e + 2);
        int2 e3 = __ldg(edges + e + 3);
        float2 x0 = __half22float2(__ldg(XR(e0.x)));
        float2 x1 = __half22float2(__ldg(XR(e1.x)));
        float2 x2 = __half22float2(__ldg(XR(e2.x)));
        float2 x3 = __half22float2(__ldg(XR(e3.x)));
        ax = fmaf(__int_as_float(e0.y), x0.x, ax);
        ay = fmaf(__int_as_float(e0.y), x0.y, ay);
        ax = fmaf(__int_as_float(e1.y), x1.x, ax);
        ay = fmaf(__int_as_float(e1.y), x1.y, ay);
        ax = fmaf(__int_as_float(e2.y), x2.x, ax);
        ay = fmaf(__int_as_float(e2.y), x2.y, ay);
        ax = fmaf(__int_as_float(e3.y), x3.x, ax);
        ay = fmaf(__int_as_float(e3.y), x3.y, ay);
    }
    for (; e < end; ++e) {
        int2 ed = __ldg(edges + e);
        float2 xv = __half22float2(__ldg(XR(ed.x)));
        float v = __int_as_float(ed.y);
        ax = fmaf(v, xv.x, ax);
        ay = fmaf(v, xv.y, ay);
    }
    #undef XR

    if (!FINAL) {
        reinterpret_cast<__half2*>(y + (size_t)warp * EMB)[lane] =
            __floats2half2_rn(ax, ay);
    } else {
        float2 eg = __half22float2(
            __ldg(reinterpret_cast<const __half2*>(ego + (size_t)warp * EMB) + lane));
        float2 a1 = __half22float2(
            __ldg(reinterpret_cast<const __half2*>(h1 + (size_t)warp * EMB) + lane));
        float2 a2 = __half22float2(
            __ldg(reinterpret_cast<const __half2*>(x + (size_t)warp * EMB) + lane));
        float2 o;
        o.x = (eg.x + a1.x + a2.x + ax) * 0.25f;
        o.y = (eg.y + a1.y + a2.y + ay) * 0.25f;
        reinterpret_cast<float2*>(out + (size_t)warp * EMB)[lane] = o;
    }
}

extern "C" void kernel_launch(void* const* d_in, const int* in_sizes, int n_in,
                              void* d_out, int out_size) {
    const float* user_emb = (const float*)d_in[0];
    const float* item_emb = (const float*)d_in[1];
    const int*   adj_row  = (const int*)  d_in[2];
    const int*   adj_col  = (const int*)  d_in[3];
    const float* adj_vals = (const float*)d_in[4];
    float* out = (float*)d_out;
    int nnz = in_sizes[2];

    __half* ego;   cudaGetSymbolAddress((void**)&ego,    g_ego);
    __half* h1;    cudaGetSymbolAddress((void**)&h1,     g_h1);
    __half* h2;    cudaGetSymbolAddress((void**)&h2,     g_h2);
    int*   rowptr; cudaGetSymbolAddress((void**)&rowptr, g_rowptr);
    int*   cursor; cudaGetSymbolAddress((void**)&cursor, g_cursor);
    int*   counts; cudaGetSymbolAddress((void**)&counts, g_counts);
    int2*  edges;  cudaGetSymbolAddress((void**)&edges,  g_edges);
    int*   partial;cudaGetSymbolAddress((void**)&partial,g_partial);
    int*   pex;    cudaGetSymbolAddress((void**)&pex,    g_pex);

    const int T = 256;
    const int CV_BLOCKS = (TOT / 2 + T - 1) / T;         // also covers N_NODES
    const int EG_BLOCKS = (nnz + T - 1) / T;
    const int SP_BLOCKS = (N_NODES * 32 + T - 1) / T;    // warp per row

    // ego fp16 copy + zero histogram
    convert_ego<<<CV_BLOCKS, T>>>((const float2*)user_emb, (const float2*)item_emb,
                                  (__half2*)ego, counts);

    // counting sort by row -> CSR (rowptr + packed (col,val) edges)
    hist_kernel<<<EG_BLOCKS, T>>>(adj_row, counts, nnz);
    scan_reduce<<<NCHUNK, SCAN_CHUNK>>>(counts, partial);
    scan_partials<<<1, 256>>>(partial, pex, NCHUNK);
    scan_final<<<NCHUNK, SCAN_CHUNK>>>(counts, pex, rowptr, cursor, nnz);
    scatter_kernel<<<EG_BLOCKS, T>>>(adj_row, adj_col, adj_vals, cursor, edges, nnz);

    // layer 1: h1 = A*ego
    spmm_csr<false><<<SP_BLOCKS, T>>>(rowptr, edges, ego, h1, nullptr, nullptr, nullptr);
    // layer 2: h2 = A*h1
    spmm_csr<false><<<SP_BLOCKS, T>>>(rowptr, edges, h1, h2, nullptr, nullptr, nullptr);
    // layer 3: out = (ego + h1 + h2 + A*h2) / 4
    spmm_csr<true><<<SP_BLOCKS, T>>>(rowptr, edges, h2, nullptr, ego, h1, out);
}

// round 8
// speedup vs baseline: 1.6374x; 1.0273x over previous
#include <cuda_runtime.h>
#include <cuda_fp16.h>
#include <cuda_bf16.h>
#include <cstdint>

#define USER_NUM 100000
#define ITEM_NUM 50000
#define N_NODES  (USER_NUM + ITEM_NUM)   // 150000
#define EMB      64
#define TOT      (N_NODES * EMB)         // 9,600,000 elements
#define USER_ELEMS (USER_NUM * EMB)
#define NNZ_MAX  4800000
#define SCAN_CHUNK 1024
#define NCHUNK   ((N_NODES + SCAN_CHUNK - 1) / SCAN_CHUNK)   // 147

// Static device scratch (no runtime allocation allowed)
__device__ __half g_ego[TOT];            // fp16 copy of concat(user,item)
__device__ __half g_h1[TOT];             // layer-1 output (fp16)
__device__ __half g_h2[TOT];             // layer-2 output (fp16)
__device__ int   g_rowptr[N_NODES + 1];
__device__ int   g_cursor[N_NODES];
__device__ int   g_counts[N_NODES];
__device__ int2  g_edges[NNZ_MAX];       // packed (col, val-bits), row-sorted
__device__ int   g_partial[256];

// ---------------------------------------------------------------------------
// zero the row histogram (tiny, must precede conv_hist)
// ---------------------------------------------------------------------------
__global__ void zero_counts(int* __restrict__ counts) {
    int i = blockIdx.x * blockDim.x + threadIdx.x;
    if (i < N_NODES) counts[i] = 0;
}

// ---------------------------------------------------------------------------
// FUSED: convert ego -> fp16  +  per-row histogram.
// TOT/2 == NNZ == 4.8M, so one grid covers both streams. The fp32 ego read
// is DRAM-bound; the hist atomics are L2-ALU-bound — good overlap.
// ---------------------------------------------------------------------------
__global__ void conv_hist(const float2* __restrict__ user2,
                          const float2* __restrict__ item2,
                          __half2* __restrict__ ego2,
                          const int* __restrict__ row,
                          int* __restrict__ counts, int nnz) {
    int i = blockIdx.x * blockDim.x + threadIdx.x;
    if (i < TOT / 2) {
        float2 v = (i < USER_ELEMS / 2) ? __ldg(user2 + i)
                                        : __ldg(item2 + (i - USER_ELEMS / 2));
        ego2[i] = __floats2half2_rn(v.x, v.y);
    }
    if (i < nnz) atomicAdd(&counts[__ldcs(row + i)], 1);
}

// ---------------------------------------------------------------------------
// Scan stage 1: per-chunk sums (147 partials)
// ---------------------------------------------------------------------------
__global__ void scan_reduce(const int* __restrict__ counts,
                            int* __restrict__ partial) {
    __shared__ int s[SCAN_CHUNK];
    int i = blockIdx.x * SCAN_CHUNK + threadIdx.x;
    s[threadIdx.x] = (i < N_NODES) ? counts[i] : 0;
    __syncthreads();
    for (int st = SCAN_CHUNK / 2; st > 0; st >>= 1) {
        if (threadIdx.x < st) s[threadIdx.x] += s[threadIdx.x + st];
        __syncthreads();
    }
    if (threadIdx.x == 0) partial[blockIdx.x] = s[0];
}

// ---------------------------------------------------------------------------
// Scan stage 2 (fused): every block redundantly scans the 147 partials in
// smem (cheap), then does its chunk's exclusive scan -> rowptr, cursor.
// ---------------------------------------------------------------------------
__global__ void scan_final(const int* __restrict__ counts,
                           const int* __restrict__ partial,
                           int* __restrict__ rowptr,
                           int* __restrict__ cursor, int nnz) {
    __shared__ int sp[256];           // inclusive scan of partials
    __shared__ int s[SCAN_CHUNK];

    if (threadIdx.x < 256) {
        int v = (threadIdx.x < NCHUNK) ? partial[threadIdx.x] : 0;
        sp[threadIdx.x] = v;
    }
    __syncthreads();
    // Hillis-Steele over 256 entries, done by first 256 threads
    for (int st = 1; st < 256; st <<= 1) {
        int t = 0;
        if (threadIdx.x < 256 && threadIdx.x >= st) t = sp[threadIdx.x - st];
        __syncthreads();
        if (threadIdx.x < 256) sp[threadIdx.x] += t;
        __syncthreads();
    }
    int block_ex = (blockIdx.x == 0) ? 0 : sp[blockIdx.x - 1];

    int i = blockIdx.x * SCAN_CHUNK + threadIdx.x;
    int v = (i < N_NODES) ? counts[i] : 0;
    s[threadIdx.x] = v;
    __syncthreads();
    for (int st = 1; st < SCAN_CHUNK; st <<= 1) {
        int t = (threadIdx.x >= st) ? s[threadIdx.x - st] : 0;
        __syncthreads();
        s[threadIdx.x] += t;
        __syncthreads();
    }
    if (i < N_NODES) {
        int ex = block_ex + s[threadIdx.x] - v;   // exclusive prefix
        rowptr[i] = ex;
        cursor[i] = ex;
    }
    if (i == 0) rowptr[N_NODES] = nnz;
}

// ---------------------------------------------------------------------------
// Counting-sort stage 3: scatter edges into row-sorted packed array
// ---------------------------------------------------------------------------
__global__ void scatter_kernel(const int* __restrict__ row,
                               const int* __restrict__ col,
                               const float* __restrict__ vals,
                               int* __restrict__ cursor,
                               int2* __restrict__ edges, int nnz) {
    int i = blockIdx.x * blockDim.x + threadIdx.x;
    if (i < nnz) {
        int r = __ldcs(row + i);
        int p = atomicAdd(&cursor[r], 1);
        edges[p] = make_int2(__ldcs(col + i), __float_as_int(__ldcs(vals + i)));
    }
}

// ---------------------------------------------------------------------------
// CSR SpMM, warp per row, fp16 gather (128 B/edge), fp32 accumulation.
// Each lane owns a __half2 (2 consecutive dims). Unroll 4 (proven; unroll 8
// regressed via cross-CTA L1tex-queue spread).
// FINAL=false: y[row] = h (fp16)
// FINAL=true : out[row] = (ego + h1 + h2 + h) * 0.25  (fp32), no y store
// ---------------------------------------------------------------------------
template<bool FINAL>
__global__ void spmm_csr(const int* __restrict__ rowptr,
                         const int2* __restrict__ edges,
                         const __half* __restrict__ x,     // gather source
                         __half* __restrict__ y,           // !FINAL
                         const __half* __restrict__ ego,   // FINAL
                         const __half* __restrict__ h1,    // FINAL
                         float* __restrict__ out) {        // FINAL
    int warp = (blockIdx.x * blockDim.x + threadIdx.x) >> 5;
    int lane = threadIdx.x & 31;
    if (warp >= N_NODES) return;

    int start = __ldg(rowptr + warp);
    int end   = __ldg(rowptr + warp + 1);

    float ax = 0.f, ay = 0.f;
    int e = start;

    #define XR(c) (reinterpret_cast<const __half2*>(x + (size_t)(c) * EMB) + lane)

    for (; e + 4 <= end; e += 4) {
        int2 e0 = __ldg(edges + e + 0);
        int2 e1 = __ldg(edges + e + 1);
        int2 e2 = __ldg(edges + e + 2);
        int2 e3 = __ldg(edges + e + 3);
        float2 x0 = __half22float2(__ldg(XR(e0.x)));
        float2 x1 = __half22float2(__ldg(XR(e1.x)));
        float2 x2 = __half22float2(__ldg(XR(e2.x)));
        float2 x3 = __half22float2(__ldg(XR(e3.x)));
        ax = fmaf(__int_as_float(e0.y), x0.x, ax);
        ay = fmaf(__int_as_float(e0.y), x0.y, ay);
        ax = fmaf(__int_as_float(e1.y), x1.x, ax);
        ay = fmaf(__int_as_float(e1.y), x1.y, ay);
        ax = fmaf(__int_as_float(e2.y), x2.x, ax);
        ay = fmaf(__int_as_float(e2.y), x2.y, ay);
        ax = fmaf(__int_as_float(e3.y), x3.x, ax);
        ay = fmaf(__int_as_float(e3.y), x3.y, ay);
    }
    for (; e < end; ++e) {
        int2 ed = __ldg(edges + e);
        float2 xv = __half22float2(__ldg(XR(ed.x)));
        float v = __int_as_float(ed.y);
        ax = fmaf(v, xv.x, ax);
        ay = fmaf(v, xv.y, ay);
    }
    #undef XR

    if (!FINAL) {
        reinterpret_cast<__half2*>(y + (size_t)warp * EMB)[lane] =
            __floats2half2_rn(ax, ay);
    } else {
        float2 eg = __half22float2(
            __ldg(reinterpret_cast<const __half2*>(ego + (size_t)warp * EMB) + lane));
        float2 a1 = __half22float2(
            __ldg(reinterpret_cast<const __half2*>(h1 + (size_t)warp * EMB) + lane));
        float2 a2 = __half22float2(
            __ldg(reinterpret_cast<const __half2*>(x + (size_t)warp * EMB) + lane));
        float2 o;
        o.x = (eg.x + a1.x + a2.x + ax) * 0.25f;
        o.y = (eg.y + a1.y + a2.y + ay) * 0.25f;
        reinterpret_cast<float2*>(out + (size_t)warp * EMB)[lane] = o;
    }
}

extern "C" void kernel_launch(void* const* d_in, const int* in_sizes, int n_in,
                              void* d_out, int out_size) {
    const float* user_emb = (const float*)d_in[0];
    const float* item_emb = (const float*)d_in[1];
    const int*   adj_row  = (const int*)  d_in[2];
    const int*   adj_col  = (const int*)  d_in[3];
    const float* adj_vals = (const float*)d_in[4];
    float* out = (float*)d_out;
    int nnz = in_sizes[2];

    __half* ego;   cudaGetSymbolAddress((void**)&ego,    g_ego);
    __half* h1;    cudaGetSymbolAddress((void**)&h1,     g_h1);
    __half* h2;    cudaGetSymbolAddress((void**)&h2,     g_h2);
    int*   rowptr; cudaGetSymbolAddress((void**)&rowptr, g_rowptr);
    int*   cursor; cudaGetSymbolAddress((void**)&cursor, g_cursor);
    int*   counts; cudaGetSymbolAddress((void**)&counts, g_counts);
    int2*  edges;  cudaGetSymbolAddress((void**)&edges,  g_edges);
    int*   partial;cudaGetSymbolAddress((void**)&partial,g_partial);

    const int T = 256;
    const int ZC_BLOCKS = (N_NODES + T - 1) / T;
    const int CH_BLOCKS = ((TOT / 2 > nnz ? TOT / 2 : nnz) + T - 1) / T;
    const int EG_BLOCKS = (nnz + T - 1) / T;
    const int SP_BLOCKS = (N_NODES * 32 + T - 1) / T;    // warp per row

    // 1) zero histogram
    zero_counts<<<ZC_BLOCKS, T>>>(counts);
    // 2) fused ego->fp16 convert + row histogram
    conv_hist<<<CH_BLOCKS, T>>>((const float2*)user_emb, (const float2*)item_emb,
                                (__half2*)ego, adj_row, counts, nnz);
    // 3) chunk sums
    scan_reduce<<<NCHUNK, SCAN_CHUNK>>>(counts, partial);
    // 4) fused partial-scan + chunk exclusive scan -> rowptr, cursor
    scan_final<<<NCHUNK, SCAN_CHUNK>>>(counts, partial, rowptr, cursor, nnz);
    // 5) scatter edges into row-sorted order
    scatter_kernel<<<EG_BLOCKS, T>>>(adj_row, adj_col, adj_vals, cursor, edges, nnz);

    // 6) layer 1: h1 = A*ego
    spmm_csr<false><<<SP_BLOCKS, T>>>(rowptr, edges, ego, h1, nullptr, nullptr, nullptr);
    // 7) layer 2: h2 = A*h1
    spmm_csr<false><<<SP_BLOCKS, T>>>(rowptr, edges, h1, h2, nullptr, nullptr, nullptr);
    // 8) layer 3: out = (ego + h1 + h2 + A*h2) / 4
    spmm_csr<true><<<SP_BLOCKS, T>>>(rowptr, edges, h2, nullptr, ego, h1, out);
}